// round 1
// baseline (speedup 1.0000x reference)
#include <cuda_runtime.h>
#include <math.h>

#define NV 200000
#define NE 50000
#define NNZp 2000000
#define FIN 256
#define DD 128

// Scratch (device globals — no allocation allowed)
__device__ float g_x0[(size_t)NV * DD];     // GEMM output / hop2 e2v accumulator
__device__ float g_xnum[(size_t)NV * DD];   // hop1 e2v accumulator
__device__ float g_ynum[(size_t)NE * DD];   // v2e accumulator (reused both hops)
__device__ float g_dene[NE];
__device__ float g_denv[NV];
__device__ float g_invdenv[NV];
__device__ float g_wb[NNZp];                // e2v_w / den_e[pair_e]
__device__ float g_wc[NNZp];                // v2e_w / den_v[pair_v]

// ---------------------------------------------------------------- zero fill
__global__ void zero_kernel(float4* __restrict__ p, int n4) {
    int i = blockIdx.x * blockDim.x + threadIdx.x;
    if (i < n4) p[i] = make_float4(0.f, 0.f, 0.f, 0.f);
}

// ---------------------------------------------------------------- denominators
__global__ void den_kernel(const int* __restrict__ pv, const int* __restrict__ pe,
                           const float* __restrict__ wv2e, const float* __restrict__ we2v) {
    int i = blockIdx.x * blockDim.x + threadIdx.x;
    if (i >= NNZp) return;
    atomicAdd(&g_dene[pe[i]], wv2e[i]);
    atomicAdd(&g_denv[pv[i]], we2v[i]);
}

__global__ void combine_kernel(const int* __restrict__ pv, const int* __restrict__ pe,
                               const float* __restrict__ wv2e, const float* __restrict__ we2v) {
    int i = blockIdx.x * blockDim.x + threadIdx.x;
    if (i >= NNZp) return;
    g_wb[i] = we2v[i] / fmaxf(g_dene[pe[i]], 1e-12f);
    g_wc[i] = wv2e[i] / fmaxf(g_denv[pv[i]], 1e-12f);
}

__global__ void invdenv_kernel() {
    int i = blockIdx.x * blockDim.x + threadIdx.x;
    if (i < NV) g_invdenv[i] = 1.f / fmaxf(g_denv[i], 1e-12f);
}

// ---------------------------------------------------------------- SGEMM  x0 = feats @ W + b
// BM=128, BN=128 (full width), BK=16, 256 threads, 8x8 per thread
__global__ void __launch_bounds__(256) gemm_kernel(const float* __restrict__ A,
                                                   const float* __restrict__ Wm,
                                                   const float* __restrict__ bias,
                                                   float* __restrict__ C) {
    __shared__ float As[16][128];
    __shared__ float Bs[16][128];
    const int tid = threadIdx.x;
    const int brow = blockIdx.x * 128;
    const int ty = tid >> 4;         // 0..15 -> row group
    const int tx = tid & 15;         // 0..15 -> col group

    float acc[8][8];
#pragma unroll
    for (int i = 0; i < 8; i++)
#pragma unroll
        for (int j = 0; j < 8; j++) acc[i][j] = 0.f;

    for (int k0 = 0; k0 < FIN; k0 += 16) {
        // A tile: 128 rows x 16 cols -> stored transposed As[k][row]
#pragma unroll
        for (int ii = 0; ii < 2; ii++) {
            int id = tid * 2 + ii;              // 0..511 float4 slots
            int r  = id >> 2;                   // 0..127
            int c4 = (id & 3) * 4;              // 0,4,8,12
            int gr = brow + r;
            float4 v = make_float4(0.f, 0.f, 0.f, 0.f);
            if (gr < NV) v = *(const float4*)(A + (size_t)gr * FIN + k0 + c4);
            As[c4 + 0][r] = v.x; As[c4 + 1][r] = v.y;
            As[c4 + 2][r] = v.z; As[c4 + 3][r] = v.w;
        }
        // B tile: 16 rows x 128 cols
#pragma unroll
        for (int ii = 0; ii < 2; ii++) {
            int id = tid * 2 + ii;              // 0..511
            int kr = id >> 5;                   // 0..15
            int c4 = (id & 31) * 4;             // 0..124
            *(float4*)&Bs[kr][c4] = *(const float4*)(Wm + (size_t)(k0 + kr) * DD + c4);
        }
        __syncthreads();
#pragma unroll
        for (int k = 0; k < 16; k++) {
            float4 a0 = *(const float4*)&As[k][ty * 8];
            float4 a1 = *(const float4*)&As[k][ty * 8 + 4];
            float4 b0 = *(const float4*)&Bs[k][tx * 8];
            float4 b1 = *(const float4*)&Bs[k][tx * 8 + 4];
            float a[8] = {a0.x, a0.y, a0.z, a0.w, a1.x, a1.y, a1.z, a1.w};
            float b[8] = {b0.x, b0.y, b0.z, b0.w, b1.x, b1.y, b1.z, b1.w};
#pragma unroll
            for (int i = 0; i < 8; i++)
#pragma unroll
                for (int j = 0; j < 8; j++) acc[i][j] = fmaf(a[i], b[j], acc[i][j]);
        }
        __syncthreads();
    }
    // epilogue + bias
#pragma unroll
    for (int i = 0; i < 8; i++) {
        int gr = brow + ty * 8 + i;
        if (gr >= NV) continue;
#pragma unroll
        for (int j = 0; j < 8; j += 4) {
            float4 o;
            o.x = acc[i][j + 0] + __ldg(bias + tx * 8 + j + 0);
            o.y = acc[i][j + 1] + __ldg(bias + tx * 8 + j + 1);
            o.z = acc[i][j + 2] + __ldg(bias + tx * 8 + j + 2);
            o.w = acc[i][j + 3] + __ldg(bias + tx * 8 + j + 3);
            *(float4*)(C + (size_t)gr * DD + tx * 8 + j) = o;
        }
    }
}

// ---------------------------------------------------------------- scatter: dst[d] += w * src[s]
// one warp per pair; lane handles one float4 of the 128-float row
__global__ void __launch_bounds__(256) scatter_kernel(const float4* __restrict__ src,
                                                      float4* __restrict__ dst,
                                                      const int* __restrict__ sidx,
                                                      const int* __restrict__ didx,
                                                      const float* __restrict__ w) {
    int t = blockIdx.x * blockDim.x + threadIdx.x;
    int p = t >> 5;
    int lane = t & 31;
    if (p >= NNZp) return;
    int s = __ldg(sidx + p);
    int d = __ldg(didx + p);
    float wt = __ldg(w + p);
    float4 v = __ldg(src + (size_t)s * 32 + lane);
    float4 m = make_float4(v.x * wt, v.y * wt, v.z * wt, v.w * wt);
    atomicAdd(dst + (size_t)d * 32 + lane, m);   // red.global.add.v4.f32 (sm_90+)
}

// ---------------------------------------------------------------- fused scale + softmax
__global__ void __launch_bounds__(256) softmax_kernel(const float4* __restrict__ xnum,
                                                      const float* __restrict__ invd,
                                                      float4* __restrict__ out) {
    int t = blockIdx.x * blockDim.x + threadIdx.x;
    int r = t >> 5;
    int lane = t & 31;
    if (r >= NV) return;
    float sc = __ldg(invd + r);
    float4 v = __ldg(xnum + (size_t)r * 32 + lane);
    v.x *= sc; v.y *= sc; v.z *= sc; v.w *= sc;
    float m = fmaxf(fmaxf(v.x, v.y), fmaxf(v.z, v.w));
#pragma unroll
    for (int o = 16; o; o >>= 1) m = fmaxf(m, __shfl_xor_sync(0xffffffffu, m, o));
    float4 e;
    e.x = __expf(v.x - m); e.y = __expf(v.y - m);
    e.z = __expf(v.z - m); e.w = __expf(v.w - m);
    float s = e.x + e.y + e.z + e.w;
#pragma unroll
    for (int o = 16; o; o >>= 1) s += __shfl_xor_sync(0xffffffffu, s, o);
    float inv = 1.f / s;
    out[(size_t)r * 32 + lane] = make_float4(e.x * inv, e.y * inv, e.z * inv, e.w * inv);
}

// ---------------------------------------------------------------- launch
extern "C" void kernel_launch(void* const* d_in, const int* in_sizes, int n_in,
                              void* d_out, int out_size) {
    const float* feats = (const float*)d_in[0];
    const float* Wm    = (const float*)d_in[1];
    const float* bias  = (const float*)d_in[2];
    const float* v2e_w = (const float*)d_in[3];
    const float* e2v_w = (const float*)d_in[4];
    const int*   pv    = (const int*)d_in[5];
    const int*   pe    = (const int*)d_in[6];
    float* out = (float*)d_out;

    float *x0, *xnum, *ynum, *wb, *wc, *invdenv, *dene, *denv;
    cudaGetSymbolAddress((void**)&x0,      g_x0);
    cudaGetSymbolAddress((void**)&xnum,    g_xnum);
    cudaGetSymbolAddress((void**)&ynum,    g_ynum);
    cudaGetSymbolAddress((void**)&wb,      g_wb);
    cudaGetSymbolAddress((void**)&wc,      g_wc);
    cudaGetSymbolAddress((void**)&invdenv, g_invdenv);
    cudaGetSymbolAddress((void**)&dene,    g_dene);
    cudaGetSymbolAddress((void**)&denv,    g_denv);

    const int TB = 256;
    const int nnzBlocks   = (NNZp + TB - 1) / TB;          // 7813
    const int scatBlocks  = (NNZp * 32) / TB;              // 250000
    const int smBlocks    = (NV * 32) / TB;                // 25000

    // denominators + folded weights (den>0 everywhere weights land; empty segments give 0*huge=0, matching ref)
    zero_kernel<<<(NE / 4 + TB - 1) / TB, TB>>>((float4*)dene, NE / 4);
    zero_kernel<<<(NV / 4 + TB - 1) / TB, TB>>>((float4*)denv, NV / 4);
    den_kernel<<<nnzBlocks, TB>>>(pv, pe, v2e_w, e2v_w);
    combine_kernel<<<nnzBlocks, TB>>>(pv, pe, v2e_w, e2v_w);
    invdenv_kernel<<<(NV + TB - 1) / TB, TB>>>();

    // x0 = feats @ W + b
    gemm_kernel<<<(NV + 127) / 128, TB>>>(feats, Wm, bias, x0);

    // hop 1
    zero_kernel<<<(NE * DD / 4) / TB, TB>>>((float4*)ynum, NE * DD / 4);
    scatter_kernel<<<scatBlocks, TB>>>((const float4*)x0, (float4*)ynum, pv, pe, v2e_w);
    zero_kernel<<<(NV * DD / 4) / TB, TB>>>((float4*)xnum, NV * DD / 4);
    scatter_kernel<<<scatBlocks, TB>>>((const float4*)ynum, (float4*)xnum, pe, pv, wb);

    // hop 2 (x0 reused as accumulator; wc folds 1/den_v of hop1, wb folds 1/den_e)
    zero_kernel<<<(NE * DD / 4) / TB, TB>>>((float4*)ynum, NE * DD / 4);
    scatter_kernel<<<scatBlocks, TB>>>((const float4*)xnum, (float4*)ynum, pv, pe, wc);
    zero_kernel<<<(NV * DD / 4) / TB, TB>>>((float4*)x0, NV * DD / 4);
    scatter_kernel<<<scatBlocks, TB>>>((const float4*)ynum, (float4*)x0, pe, pv, wb);

    // final 1/den_v scale fused into softmax
    softmax_kernel<<<smBlocks, TB>>>((const float4*)x0, invdenv, (float4*)out);
}

// round 4
// speedup vs baseline: 1.7772x; 1.7772x over previous
#include <cuda_runtime.h>
#include <math.h>

#define NV 200000
#define NE 50000
#define NNZp 2000000
#define FIN 256
#define DD 128

// ---------------- device scratch (no allocation allowed) ----------------
__device__ float g_x0[(size_t)NV * DD];     // GEMM output / final accumulator
__device__ float g_x1[(size_t)NV * DD];     // intermediate vertex features
__device__ float g_y[(size_t)NE * DD];      // edge features
__device__ int   g_cnt_e[NE];
__device__ int   g_cnt_v[NV];
__device__ float g_den_e[NE];
__device__ float g_den_v[NV];
__device__ float g_invdene[NE];
__device__ float g_invdenv[NV];
__device__ int   g_off_e[NE + 1];
__device__ int   g_off_v[NV + 1];
__device__ int   g_cur_e[NE + 1];
__device__ int   g_cur_v[NV + 1];
__device__ int   g_esrc[NNZp];   // vertex ids grouped by edge
__device__ float g_ew[NNZp];     // v2e weights grouped by edge
__device__ int   g_vsrc[NNZp];   // edge ids grouped by vertex
__device__ float g_vw[NNZp];     // e2v weights grouped by vertex
__device__ int   g_scan_tmp[NV]; // inclusive-scan scratch
__device__ int   g_bsums[256];

// ---------------- zero counters/denominators ----------------
__global__ void zero_small_kernel() {
    int i = blockIdx.x * blockDim.x + threadIdx.x;
    if (i < NE) { g_cnt_e[i] = 0; g_den_e[i] = 0.f; }
    if (i < NV) { g_cnt_v[i] = 0; g_den_v[i] = 0.f; }
}

// ---------------- histogram + denominators ----------------
__global__ void count_den_kernel(const int* __restrict__ pv, const int* __restrict__ pe,
                                 const float* __restrict__ wv2e, const float* __restrict__ we2v) {
    int i = blockIdx.x * blockDim.x + threadIdx.x;
    if (i >= NNZp) return;
    int v = pv[i], e = pe[i];
    atomicAdd(&g_cnt_e[e], 1);
    atomicAdd(&g_den_e[e], wv2e[i]);
    atomicAdd(&g_cnt_v[v], 1);
    atomicAdd(&g_den_v[v], we2v[i]);
}

__global__ void invden_kernel() {
    int i = blockIdx.x * blockDim.x + threadIdx.x;
    if (i < NE) g_invdene[i] = 1.f / fmaxf(g_den_e[i], 1e-12f);
    if (i < NV) g_invdenv[i] = 1.f / fmaxf(g_den_v[i], 1e-12f);
}

// ---------------- scan (1024 elems per block) ----------------
__global__ void scan_chunk_kernel(const int* __restrict__ in, int* __restrict__ incl,
                                  int* __restrict__ bsums, int n) {
    __shared__ int sh[256];
    int t = threadIdx.x;
    int base = blockIdx.x * 1024 + t * 4;
    int a0 = (base + 0 < n) ? in[base + 0] : 0;
    int a1 = (base + 1 < n) ? in[base + 1] : 0;
    int a2 = (base + 2 < n) ? in[base + 2] : 0;
    int a3 = (base + 3 < n) ? in[base + 3] : 0;
    int s1 = a0 + a1, s2 = s1 + a2, s3 = s2 + a3;
    sh[t] = s3;
    __syncthreads();
#pragma unroll
    for (int o = 1; o < 256; o <<= 1) {
        int v = (t >= o) ? sh[t - o] : 0;
        __syncthreads();
        sh[t] += v;
        __syncthreads();
    }
    int excl = sh[t] - s3;
    if (base + 0 < n) incl[base + 0] = excl + a0;
    if (base + 1 < n) incl[base + 1] = excl + s1;
    if (base + 2 < n) incl[base + 2] = excl + s2;
    if (base + 3 < n) incl[base + 3] = excl + s3;
    if (t == 255) bsums[blockIdx.x] = sh[255];
}

__global__ void scan_bsums_kernel(int* __restrict__ bsums, int nb) {
    __shared__ int sh[256];
    int t = threadIdx.x;
    int v = (t < nb) ? bsums[t] : 0;
    sh[t] = v;
    __syncthreads();
#pragma unroll
    for (int o = 1; o < 256; o <<= 1) {
        int u = (t >= o) ? sh[t - o] : 0;
        __syncthreads();
        sh[t] += u;
        __syncthreads();
    }
    if (t < nb) bsums[t] = sh[t] - v;   // exclusive
}

__global__ void finalize_off_kernel(const int* __restrict__ incl, const int* __restrict__ bexcl,
                                    int* __restrict__ off, int* __restrict__ cur, int n) {
    int i = blockIdx.x * blockDim.x + threadIdx.x;
    if (i >= n) return;
    int val = incl[i] + bexcl[i >> 10];
    off[i + 1] = val;
    cur[i + 1] = val;
    if (i == 0) { off[0] = 0; cur[0] = 0; }
}

// ---------------- fill CSR-style permuted arrays ----------------
__global__ void fill_kernel(const int* __restrict__ pv, const int* __restrict__ pe,
                            const float* __restrict__ wv2e, const float* __restrict__ we2v) {
    int i = blockIdx.x * blockDim.x + threadIdx.x;
    if (i >= NNZp) return;
    int v = pv[i], e = pe[i];
    int pe_pos = atomicAdd(&g_cur_e[e], 1);
    g_esrc[pe_pos] = v;
    g_ew[pe_pos]   = wv2e[i];
    int pv_pos = atomicAdd(&g_cur_v[v], 1);
    g_vsrc[pv_pos] = e;
    g_vw[pv_pos]   = we2v[i];
}

// ---------------- SGEMM  x0 = feats @ W + b ----------------
__global__ void __launch_bounds__(256) gemm_kernel(const float* __restrict__ A,
                                                   const float* __restrict__ Wm,
                                                   const float* __restrict__ bias,
                                                   float* __restrict__ C) {
    __shared__ float As[16][128];
    __shared__ float Bs[16][128];
    const int tid = threadIdx.x;
    const int brow = blockIdx.x * 128;
    const int ty = tid >> 4;
    const int tx = tid & 15;

    float acc[8][8];
#pragma unroll
    for (int i = 0; i < 8; i++)
#pragma unroll
        for (int j = 0; j < 8; j++) acc[i][j] = 0.f;

    for (int k0 = 0; k0 < FIN; k0 += 16) {
#pragma unroll
        for (int ii = 0; ii < 2; ii++) {
            int id = tid * 2 + ii;
            int r  = id >> 2;
            int c4 = (id & 3) * 4;
            int gr = brow + r;
            float4 v = make_float4(0.f, 0.f, 0.f, 0.f);
            if (gr < NV) v = *(const float4*)(A + (size_t)gr * FIN + k0 + c4);
            As[c4 + 0][r] = v.x; As[c4 + 1][r] = v.y;
            As[c4 + 2][r] = v.z; As[c4 + 3][r] = v.w;
        }
#pragma unroll
        for (int ii = 0; ii < 2; ii++) {
            int id = tid * 2 + ii;
            int kr = id >> 5;
            int c4 = (id & 31) * 4;
            *(float4*)&Bs[kr][c4] = *(const float4*)(Wm + (size_t)(k0 + kr) * DD + c4);
        }
        __syncthreads();
#pragma unroll
        for (int k = 0; k < 16; k++) {
            float4 a0 = *(const float4*)&As[k][ty * 8];
            float4 a1 = *(const float4*)&As[k][ty * 8 + 4];
            float4 b0 = *(const float4*)&Bs[k][tx * 8];
            float4 b1 = *(const float4*)&Bs[k][tx * 8 + 4];
            float a[8] = {a0.x, a0.y, a0.z, a0.w, a1.x, a1.y, a1.z, a1.w};
            float b[8] = {b0.x, b0.y, b0.z, b0.w, b1.x, b1.y, b1.z, b1.w};
#pragma unroll
            for (int i = 0; i < 8; i++)
#pragma unroll
                for (int j = 0; j < 8; j++) acc[i][j] = fmaf(a[i], b[j], acc[i][j]);
        }
        __syncthreads();
    }
#pragma unroll
    for (int i = 0; i < 8; i++) {
        int gr = brow + ty * 8 + i;
        if (gr >= NV) continue;
#pragma unroll
        for (int j = 0; j < 8; j += 4) {
            float4 o;
            o.x = acc[i][j + 0] + __ldg(bias + tx * 8 + j + 0);
            o.y = acc[i][j + 1] + __ldg(bias + tx * 8 + j + 1);
            o.z = acc[i][j + 2] + __ldg(bias + tx * 8 + j + 2);
            o.w = acc[i][j + 3] + __ldg(bias + tx * 8 + j + 3);
            *(float4*)(C + (size_t)gr * DD + tx * 8 + j) = o;
        }
    }
}

// ---------------- gather-based weighted-mean aggregation ----------------
// one warp per destination row; lane handles one float4 of 128 floats
__global__ void __launch_bounds__(256) agg_kernel(const float4* __restrict__ src,
                                                  float4* __restrict__ dst,
                                                  const int* __restrict__ off,
                                                  const int* __restrict__ sidx,
                                                  const float* __restrict__ wt,
                                                  const float* __restrict__ invden,
                                                  int ndst) {
    int t = blockIdx.x * blockDim.x + threadIdx.x;
    int r = t >> 5;
    int lane = t & 31;
    if (r >= ndst) return;
    int j0 = __ldg(off + r);
    int j1 = __ldg(off + r + 1);
    float4 acc = make_float4(0.f, 0.f, 0.f, 0.f);
    int j = j0;
    for (; j + 2 <= j1; j += 2) {
        int   s0 = __ldg(sidx + j),   s1 = __ldg(sidx + j + 1);
        float w0 = __ldg(wt + j),     w1 = __ldg(wt + j + 1);
        float4 v0 = __ldg(src + (size_t)s0 * 32 + lane);
        float4 v1 = __ldg(src + (size_t)s1 * 32 + lane);
        acc.x = fmaf(w0, v0.x, acc.x); acc.y = fmaf(w0, v0.y, acc.y);
        acc.z = fmaf(w0, v0.z, acc.z); acc.w = fmaf(w0, v0.w, acc.w);
        acc.x = fmaf(w1, v1.x, acc.x); acc.y = fmaf(w1, v1.y, acc.y);
        acc.z = fmaf(w1, v1.z, acc.z); acc.w = fmaf(w1, v1.w, acc.w);
    }
    if (j < j1) {
        int   s0 = __ldg(sidx + j);
        float w0 = __ldg(wt + j);
        float4 v0 = __ldg(src + (size_t)s0 * 32 + lane);
        acc.x = fmaf(w0, v0.x, acc.x); acc.y = fmaf(w0, v0.y, acc.y);
        acc.z = fmaf(w0, v0.z, acc.z); acc.w = fmaf(w0, v0.w, acc.w);
    }
    float sc = __ldg(invden + r);
    acc.x *= sc; acc.y *= sc; acc.z *= sc; acc.w *= sc;
    dst[(size_t)r * 32 + lane] = acc;
}

// ---------------- fused softmax ----------------
__global__ void __launch_bounds__(256) softmax_kernel(const float4* __restrict__ x,
                                                      float4* __restrict__ out) {
    int t = blockIdx.x * blockDim.x + threadIdx.x;
    int r = t >> 5;
    int lane = t & 31;
    if (r >= NV) return;
    float4 v = __ldg(x + (size_t)r * 32 + lane);
    float m = fmaxf(fmaxf(v.x, v.y), fmaxf(v.z, v.w));
#pragma unroll
    for (int o = 16; o; o >>= 1) m = fmaxf(m, __shfl_xor_sync(0xffffffffu, m, o));
    float4 e;
    e.x = __expf(v.x - m); e.y = __expf(v.y - m);
    e.z = __expf(v.z - m); e.w = __expf(v.w - m);
    float s = e.x + e.y + e.z + e.w;
#pragma unroll
    for (int o = 16; o; o >>= 1) s += __shfl_xor_sync(0xffffffffu, s, o);
    float inv = 1.f / s;
    out[(size_t)r * 32 + lane] = make_float4(e.x * inv, e.y * inv, e.z * inv, e.w * inv);
}

// ---------------- launch ----------------
extern "C" void kernel_launch(void* const* d_in, const int* in_sizes, int n_in,
                              void* d_out, int out_size) {
    const float* feats = (const float*)d_in[0];
    const float* Wm    = (const float*)d_in[1];
    const float* bias  = (const float*)d_in[2];
    const float* v2e_w = (const float*)d_in[3];
    const float* e2v_w = (const float*)d_in[4];
    const int*   pv    = (const int*)d_in[5];
    const int*   pe    = (const int*)d_in[6];
    float* out = (float*)d_out;

    float *x0, *x1, *y, *invdene, *invdenv, *ew, *vw;
    int *cnt_e, *cnt_v, *off_e, *off_v, *cur_e, *cur_v, *esrc, *vsrc, *scan_tmp, *bsums;
    cudaGetSymbolAddress((void**)&x0, g_x0);
    cudaGetSymbolAddress((void**)&x1, g_x1);
    cudaGetSymbolAddress((void**)&y,  g_y);
    cudaGetSymbolAddress((void**)&invdene, g_invdene);
    cudaGetSymbolAddress((void**)&invdenv, g_invdenv);
    cudaGetSymbolAddress((void**)&ew, g_ew);
    cudaGetSymbolAddress((void**)&vw, g_vw);
    cudaGetSymbolAddress((void**)&cnt_e, g_cnt_e);
    cudaGetSymbolAddress((void**)&cnt_v, g_cnt_v);
    cudaGetSymbolAddress((void**)&off_e, g_off_e);
    cudaGetSymbolAddress((void**)&off_v, g_off_v);
    cudaGetSymbolAddress((void**)&cur_e, g_cur_e);
    cudaGetSymbolAddress((void**)&cur_v, g_cur_v);
    cudaGetSymbolAddress((void**)&esrc, g_esrc);
    cudaGetSymbolAddress((void**)&vsrc, g_vsrc);
    cudaGetSymbolAddress((void**)&scan_tmp, g_scan_tmp);
    cudaGetSymbolAddress((void**)&bsums, g_bsums);

    const int TB = 256;
    const int nnzBlocks = (NNZp + TB - 1) / TB;

    // 1) counts + denominators
    zero_small_kernel<<<(NV + TB - 1) / TB, TB>>>();
    count_den_kernel<<<nnzBlocks, TB>>>(pv, pe, v2e_w, e2v_w);
    invden_kernel<<<(NV + TB - 1) / TB, TB>>>();

    // 2) offsets via scan (edge side)
    {
        int nb = (NE + 1023) / 1024;   // 49
        scan_chunk_kernel<<<nb, 256>>>(cnt_e, scan_tmp, bsums, NE);
        scan_bsums_kernel<<<1, 256>>>(bsums, nb);
        finalize_off_kernel<<<(NE + TB - 1) / TB, TB>>>(scan_tmp, bsums, off_e, cur_e, NE);
    }
    // vertex side
    {
        int nb = (NV + 1023) / 1024;   // 196
        scan_chunk_kernel<<<nb, 256>>>(cnt_v, scan_tmp, bsums, NV);
        scan_bsums_kernel<<<1, 256>>>(bsums, nb);
        finalize_off_kernel<<<(NV + TB - 1) / TB, TB>>>(scan_tmp, bsums, off_v, cur_v, NV);
    }

    // 3) fill grouped arrays
    fill_kernel<<<nnzBlocks, TB>>>(pv, pe, v2e_w, e2v_w);

    // 4) x0 = feats @ W + b
    gemm_kernel<<<(NV + 127) / 128, TB>>>(feats, Wm, bias, x0);

    // 5) two hops of weighted-mean aggregation (gather form, mean applied per pass)
    const int eBlocks = (NE * 32) / TB;   // 6250
    const int vBlocks = (NV * 32) / TB;   // 25000
    agg_kernel<<<eBlocks, TB>>>((const float4*)x0, (float4*)y,  off_e, esrc, ew, invdene, NE);
    agg_kernel<<<vBlocks, TB>>>((const float4*)y,  (float4*)x1, off_v, vsrc, vw, invdenv, NV);
    agg_kernel<<<eBlocks, TB>>>((const float4*)x1, (float4*)y,  off_e, esrc, ew, invdene, NE);
    agg_kernel<<<vBlocks, TB>>>((const float4*)y,  (float4*)x0, off_v, vsrc, vw, invdenv, NV);

    // 6) softmax
    softmax_kernel<<<vBlocks, TB>>>((const float4*)x0, (float4*)out);
}

// round 6
// speedup vs baseline: 1.8412x; 1.0360x over previous
#include <cuda_runtime.h>
#include <math.h>

#define NV 200000
#define NE 50000
#define NNZp 2000000
#define FIN 256
#define DD 128

// ---------------- device scratch (no allocation allowed) ----------------
__device__ float g_x0[(size_t)NV * DD];     // GEMM output / final accumulator
__device__ float g_x1[(size_t)NV * DD];     // intermediate vertex features
__device__ float g_y[(size_t)NE * DD];      // edge features
__device__ int   g_cnt_e[NE];
__device__ int   g_cnt_v[NV];
__device__ float g_den_e[NE];
__device__ float g_den_v[NV];
__device__ float g_invdene[NE];
__device__ float g_invdenv[NV];
__device__ int   g_off_e[NE + 1];
__device__ int   g_off_v[NV + 1];
__device__ int   g_cur_e[NE + 1];
__device__ int   g_cur_v[NV + 1];
__device__ int   g_esrc[NNZp];   // vertex ids grouped by edge
__device__ float g_ew[NNZp];     // v2e weights grouped by edge
__device__ int   g_vsrc[NNZp];   // edge ids grouped by vertex
__device__ float g_vw[NNZp];     // e2v weights grouped by vertex
__device__ int   g_scan_tmp[NV]; // inclusive-scan scratch
__device__ int   g_bsums[256];

// ---------------- zero counters/denominators ----------------
__global__ void zero_small_kernel() {
    int i = blockIdx.x * blockDim.x + threadIdx.x;
    if (i < NE) { g_cnt_e[i] = 0; g_den_e[i] = 0.f; }
    if (i < NV) { g_cnt_v[i] = 0; g_den_v[i] = 0.f; }
}

// ---------------- histogram + denominators ----------------
__global__ void count_den_kernel(const int* __restrict__ pv, const int* __restrict__ pe,
                                 const float* __restrict__ wv2e, const float* __restrict__ we2v) {
    int i = blockIdx.x * blockDim.x + threadIdx.x;
    if (i >= NNZp) return;
    int v = pv[i], e = pe[i];
    atomicAdd(&g_cnt_e[e], 1);
    atomicAdd(&g_den_e[e], wv2e[i]);
    atomicAdd(&g_cnt_v[v], 1);
    atomicAdd(&g_den_v[v], we2v[i]);
}

__global__ void invden_kernel() {
    int i = blockIdx.x * blockDim.x + threadIdx.x;
    if (i < NE) g_invdene[i] = 1.f / fmaxf(g_den_e[i], 1e-12f);
    if (i < NV) g_invdenv[i] = 1.f / fmaxf(g_den_v[i], 1e-12f);
}

// ---------------- scan (1024 elems per block) ----------------
__global__ void scan_chunk_kernel(const int* __restrict__ in, int* __restrict__ incl,
                                  int* __restrict__ bsums, int n) {
    __shared__ int sh[256];
    int t = threadIdx.x;
    int base = blockIdx.x * 1024 + t * 4;
    int a0 = (base + 0 < n) ? in[base + 0] : 0;
    int a1 = (base + 1 < n) ? in[base + 1] : 0;
    int a2 = (base + 2 < n) ? in[base + 2] : 0;
    int a3 = (base + 3 < n) ? in[base + 3] : 0;
    int s1 = a0 + a1, s2 = s1 + a2, s3 = s2 + a3;
    sh[t] = s3;
    __syncthreads();
#pragma unroll
    for (int o = 1; o < 256; o <<= 1) {
        int v = (t >= o) ? sh[t - o] : 0;
        __syncthreads();
        sh[t] += v;
        __syncthreads();
    }
    int excl = sh[t] - s3;
    if (base + 0 < n) incl[base + 0] = excl + a0;
    if (base + 1 < n) incl[base + 1] = excl + s1;
    if (base + 2 < n) incl[base + 2] = excl + s2;
    if (base + 3 < n) incl[base + 3] = excl + s3;
    if (t == 255) bsums[blockIdx.x] = sh[255];
}

__global__ void scan_bsums_kernel(int* __restrict__ bsums, int nb) {
    __shared__ int sh[256];
    int t = threadIdx.x;
    int v = (t < nb) ? bsums[t] : 0;
    sh[t] = v;
    __syncthreads();
#pragma unroll
    for (int o = 1; o < 256; o <<= 1) {
        int u = (t >= o) ? sh[t - o] : 0;
        __syncthreads();
        sh[t] += u;
        __syncthreads();
    }
    if (t < nb) bsums[t] = sh[t] - v;   // exclusive
}

__global__ void finalize_off_kernel(const int* __restrict__ incl, const int* __restrict__ bexcl,
                                    int* __restrict__ off, int* __restrict__ cur, int n) {
    int i = blockIdx.x * blockDim.x + threadIdx.x;
    if (i >= n) return;
    int val = incl[i] + bexcl[i >> 10];
    off[i + 1] = val;
    cur[i + 1] = val;
    if (i == 0) { off[0] = 0; cur[0] = 0; }
}

// ---------------- fill CSR-style permuted arrays ----------------
__global__ void fill_kernel(const int* __restrict__ pv, const int* __restrict__ pe,
                            const float* __restrict__ wv2e, const float* __restrict__ we2v) {
    int i = blockIdx.x * blockDim.x + threadIdx.x;
    if (i >= NNZp) return;
    int v = pv[i], e = pe[i];
    int pe_pos = atomicAdd(&g_cur_e[e], 1);
    g_esrc[pe_pos] = v;
    g_ew[pe_pos]   = wv2e[i];
    int pv_pos = atomicAdd(&g_cur_v[v], 1);
    g_vsrc[pv_pos] = e;
    g_vw[pv_pos]   = we2v[i];
}

// ---------------- SGEMM  x0 = feats @ W + b  (packed f32x2 FFMA2 path) ----------------
// BM=128, BN=128, BK=16, 256 threads, 8x8 per thread.
// Accumulators held as 32 packed f32x2 (pairs along N); B pairs loaded directly
// from shared as 64-bit words; A element broadcast-packed once per (i,k).
__global__ void __launch_bounds__(256) gemm_kernel(const float* __restrict__ A,
                                                   const float* __restrict__ Wm,
                                                   const float* __restrict__ bias,
                                                   float* __restrict__ C) {
    __shared__ float As[16][128];
    __shared__ float Bs[16][128];
    const int tid = threadIdx.x;
    const int brow = blockIdx.x * 128;
    const int ty = tid >> 4;
    const int tx = tid & 15;

    unsigned long long acc64[8][4];
#pragma unroll
    for (int i = 0; i < 8; i++)
#pragma unroll
        for (int jp = 0; jp < 4; jp++) acc64[i][jp] = 0ULL;   // (0.f, 0.f)

    for (int k0 = 0; k0 < FIN; k0 += 16) {
#pragma unroll
        for (int ii = 0; ii < 2; ii++) {
            int id = tid * 2 + ii;
            int r  = id >> 2;
            int c4 = (id & 3) * 4;
            int gr = brow + r;
            float4 v = make_float4(0.f, 0.f, 0.f, 0.f);
            if (gr < NV) v = *(const float4*)(A + (size_t)gr * FIN + k0 + c4);
            As[c4 + 0][r] = v.x; As[c4 + 1][r] = v.y;
            As[c4 + 2][r] = v.z; As[c4 + 3][r] = v.w;
        }
#pragma unroll
        for (int ii = 0; ii < 2; ii++) {
            int id = tid * 2 + ii;
            int kr = id >> 5;
            int c4 = (id & 31) * 4;
            *(float4*)&Bs[kr][c4] = *(const float4*)(Wm + (size_t)(k0 + kr) * DD + c4);
        }
        __syncthreads();
#pragma unroll
        for (int k = 0; k < 16; k++) {
            float4 a0 = *(const float4*)&As[k][ty * 8];
            float4 a1 = *(const float4*)&As[k][ty * 8 + 4];
            float a[8] = {a0.x, a0.y, a0.z, a0.w, a1.x, a1.y, a1.z, a1.w};
            // B pairs straight from shared as 64-bit packed f32x2
            const longlong2* bp = (const longlong2*)&Bs[k][tx * 8];
            longlong2 b01 = bp[0];
            longlong2 b23 = bp[1];
            unsigned long long b64[4] = {
                (unsigned long long)b01.x, (unsigned long long)b01.y,
                (unsigned long long)b23.x, (unsigned long long)b23.y };
#pragma unroll
            for (int i = 0; i < 8; i++) {
                unsigned long long a2;
                unsigned int ai = __float_as_uint(a[i]);
                asm("mov.b64 %0, {%1, %1};" : "=l"(a2) : "r"(ai));
#pragma unroll
                for (int jp = 0; jp < 4; jp++)
                    asm("fma.rn.f32x2 %0, %1, %2, %0;"
                        : "+l"(acc64[i][jp]) : "l"(a2), "l"(b64[jp]));
            }
        }
        __syncthreads();
    }
    // epilogue: unpack + bias
#pragma unroll
    for (int i = 0; i < 8; i++) {
        int gr = brow + ty * 8 + i;
        if (gr >= NV) continue;
#pragma unroll
        for (int jh = 0; jh < 2; jh++) {
            unsigned int l0, h0, l1, h1;
            asm("mov.b64 {%0, %1}, %2;" : "=r"(l0), "=r"(h0) : "l"(acc64[i][jh * 2 + 0]));
            asm("mov.b64 {%0, %1}, %2;" : "=r"(l1), "=r"(h1) : "l"(acc64[i][jh * 2 + 1]));
            int j = jh * 4;
            float4 o;
            o.x = __uint_as_float(l0) + __ldg(bias + tx * 8 + j + 0);
            o.y = __uint_as_float(h0) + __ldg(bias + tx * 8 + j + 1);
            o.z = __uint_as_float(l1) + __ldg(bias + tx * 8 + j + 2);
            o.w = __uint_as_float(h1) + __ldg(bias + tx * 8 + j + 3);
            *(float4*)(C + (size_t)gr * DD + tx * 8 + j) = o;
        }
    }
}

// ---------------- gather-based weighted-mean aggregation ----------------
// one warp per destination row; lane handles one float4 of 128 floats
__global__ void __launch_bounds__(256) agg_kernel(const float4* __restrict__ src,
                                                  float4* __restrict__ dst,
                                                  const int* __restrict__ off,
                                                  const int* __restrict__ sidx,
                                                  const float* __restrict__ wt,
                                                  const float* __restrict__ invden,
                                                  int ndst) {
    int t = blockIdx.x * blockDim.x + threadIdx.x;
    int r = t >> 5;
    int lane = t & 31;
    if (r >= ndst) return;
    int j0 = __ldg(off + r);
    int j1 = __ldg(off + r + 1);
    float4 acc = make_float4(0.f, 0.f, 0.f, 0.f);
    int j = j0;
    for (; j + 2 <= j1; j += 2) {
        int   s0 = __ldg(sidx + j),   s1 = __ldg(sidx + j + 1);
        float w0 = __ldg(wt + j),     w1 = __ldg(wt + j + 1);
        float4 v0 = __ldg(src + (size_t)s0 * 32 + lane);
        float4 v1 = __ldg(src + (size_t)s1 * 32 + lane);
        acc.x = fmaf(w0, v0.x, acc.x); acc.y = fmaf(w0, v0.y, acc.y);
        acc.z = fmaf(w0, v0.z, acc.z); acc.w = fmaf(w0, v0.w, acc.w);
        acc.x = fmaf(w1, v1.x, acc.x); acc.y = fmaf(w1, v1.y, acc.y);
        acc.z = fmaf(w1, v1.z, acc.z); acc.w = fmaf(w1, v1.w, acc.w);
    }
    if (j < j1) {
        int   s0 = __ldg(sidx + j);
        float w0 = __ldg(wt + j);
        float4 v0 = __ldg(src + (size_t)s0 * 32 + lane);
        acc.x = fmaf(w0, v0.x, acc.x); acc.y = fmaf(w0, v0.y, acc.y);
        acc.z = fmaf(w0, v0.z, acc.z); acc.w = fmaf(w0, v0.w, acc.w);
    }
    float sc = __ldg(invden + r);
    acc.x *= sc; acc.y *= sc; acc.z *= sc; acc.w *= sc;
    dst[(size_t)r * 32 + lane] = acc;
}

// ---------------- fused softmax ----------------
__global__ void __launch_bounds__(256) softmax_kernel(const float4* __restrict__ x,
                                                      float4* __restrict__ out) {
    int t = blockIdx.x * blockDim.x + threadIdx.x;
    int r = t >> 5;
    int lane = t & 31;
    if (r >= NV) return;
    float4 v = __ldg(x + (size_t)r * 32 + lane);
    float m = fmaxf(fmaxf(v.x, v.y), fmaxf(v.z, v.w));
#pragma unroll
    for (int o = 16; o; o >>= 1) m = fmaxf(m, __shfl_xor_sync(0xffffffffu, m, o));
    float4 e;
    e.x = __expf(v.x - m); e.y = __expf(v.y - m);
    e.z = __expf(v.z - m); e.w = __expf(v.w - m);
    float s = e.x + e.y + e.z + e.w;
#pragma unroll
    for (int o = 16; o; o >>= 1) s += __shfl_xor_sync(0xffffffffu, s, o);
    float inv = 1.f / s;
    out[(size_t)r * 32 + lane] = make_float4(e.x * inv, e.y * inv, e.z * inv, e.w * inv);
}

// ---------------- launch ----------------
extern "C" void kernel_launch(void* const* d_in, const int* in_sizes, int n_in,
                              void* d_out, int out_size) {
    const float* feats = (const float*)d_in[0];
    const float* Wm    = (const float*)d_in[1];
    const float* bias  = (const float*)d_in[2];
    const float* v2e_w = (const float*)d_in[3];
    const float* e2v_w = (const float*)d_in[4];
    const int*   pv    = (const int*)d_in[5];
    const int*   pe    = (const int*)d_in[6];
    float* out = (float*)d_out;

    float *x0, *x1, *y, *invdene, *invdenv, *ew, *vw;
    int *cnt_e, *cnt_v, *off_e, *off_v, *cur_e, *cur_v, *esrc, *vsrc, *scan_tmp, *bsums;
    cudaGetSymbolAddress((void**)&x0, g_x0);
    cudaGetSymbolAddress((void**)&x1, g_x1);
    cudaGetSymbolAddress((void**)&y,  g_y);
    cudaGetSymbolAddress((void**)&invdene, g_invdene);
    cudaGetSymbolAddress((void**)&invdenv, g_invdenv);
    cudaGetSymbolAddress((void**)&ew, g_ew);
    cudaGetSymbolAddress((void**)&vw, g_vw);
    cudaGetSymbolAddress((void**)&cnt_e, g_cnt_e);
    cudaGetSymbolAddress((void**)&cnt_v, g_cnt_v);
    cudaGetSymbolAddress((void**)&off_e, g_off_e);
    cudaGetSymbolAddress((void**)&off_v, g_off_v);
    cudaGetSymbolAddress((void**)&cur_e, g_cur_e);
    cudaGetSymbolAddress((void**)&cur_v, g_cur_v);
    cudaGetSymbolAddress((void**)&esrc, g_esrc);
    cudaGetSymbolAddress((void**)&vsrc, g_vsrc);
    cudaGetSymbolAddress((void**)&scan_tmp, g_scan_tmp);
    cudaGetSymbolAddress((void**)&bsums, g_bsums);

    const int TB = 256;
    const int nnzBlocks = (NNZp + TB - 1) / TB;

    // 1) counts + denominators
    zero_small_kernel<<<(NV + TB - 1) / TB, TB>>>();
    count_den_kernel<<<nnzBlocks, TB>>>(pv, pe, v2e_w, e2v_w);
    invden_kernel<<<(NV + TB - 1) / TB, TB>>>();

    // 2) offsets via scan (edge side)
    {
        int nb = (NE + 1023) / 1024;   // 49
        scan_chunk_kernel<<<nb, 256>>>(cnt_e, scan_tmp, bsums, NE);
        scan_bsums_kernel<<<1, 256>>>(bsums, nb);
        finalize_off_kernel<<<(NE + TB - 1) / TB, TB>>>(scan_tmp, bsums, off_e, cur_e, NE);
    }
    // vertex side
    {
        int nb = (NV + 1023) / 1024;   // 196
        scan_chunk_kernel<<<nb, 256>>>(cnt_v, scan_tmp, bsums, NV);
        scan_bsums_kernel<<<1, 256>>>(bsums, nb);
        finalize_off_kernel<<<(NV + TB - 1) / TB, TB>>>(scan_tmp, bsums, off_v, cur_v, NV);
    }

    // 3) fill grouped arrays
    fill_kernel<<<nnzBlocks, TB>>>(pv, pe, v2e_w, e2v_w);

    // 4) x0 = feats @ W + b   (FFMA2 path)
    gemm_kernel<<<(NV + 127) / 128, TB>>>(feats, Wm, bias, x0);

    // 5) two hops of weighted-mean aggregation (gather form, mean applied per pass)
    const int eBlocks = (NE * 32) / TB;   // 6250
    const int vBlocks = (NV * 32) / TB;   // 25000
    agg_kernel<<<eBlocks, TB>>>((const float4*)x0, (float4*)y,  off_e, esrc, ew, invdene, NE);
    agg_kernel<<<vBlocks, TB>>>((const float4*)y,  (float4*)x1, off_v, vsrc, vw, invdenv, NV);
    agg_kernel<<<eBlocks, TB>>>((const float4*)x1, (float4*)y,  off_e, esrc, ew, invdene, NE);
    agg_kernel<<<vBlocks, TB>>>((const float4*)y,  (float4*)x0, off_v, vsrc, vw, invdenv, NV);

    // 6) softmax
    softmax_kernel<<<vBlocks, TB>>>((const float4*)x0, (float4*)out);
}

// round 8
// speedup vs baseline: 2.3871x; 1.2965x over previous
#include <cuda_runtime.h>
#include <cuda_bf16.h>
#include <math.h>

#define NV 200000
#define NE 50000
#define NNZp 2000000
#define FIN 256
#define DD 128

// ---------------- device scratch (no allocation allowed) ----------------
__device__ float g_x0[(size_t)NV * DD];
__device__ float g_x1[(size_t)NV * DD];
__device__ float g_y[(size_t)NE * DD];
__device__ int   g_cnt_e[NE];
__device__ int   g_cnt_v[NV];
__device__ float g_den_e[NE];
__device__ float g_den_v[NV];
__device__ float g_invdene[NE];
__device__ float g_invdenv[NV];
__device__ int   g_off_e[NE + 1];
__device__ int   g_off_v[NV + 1];
__device__ int   g_cur_e[NE + 1];
__device__ int   g_cur_v[NV + 1];
__device__ int   g_esrc[NNZp];
__device__ float g_ew[NNZp];
__device__ int   g_vsrc[NNZp];
__device__ float g_vw[NNZp];
__device__ int   g_scan_tmp[NV];
__device__ int   g_bsums[256];
__device__ __nv_bfloat16 g_Wth[DD * FIN];   // W transposed [n][k], hi part
__device__ __nv_bfloat16 g_Wtl[DD * FIN];   // W transposed [n][k], lo part

// ---------------- zero counters/denominators ----------------
__global__ void zero_small_kernel() {
    int i = blockIdx.x * blockDim.x + threadIdx.x;
    if (i < NE) { g_cnt_e[i] = 0; g_den_e[i] = 0.f; }
    if (i < NV) { g_cnt_v[i] = 0; g_den_v[i] = 0.f; }
}

// ---------------- histogram + denominators ----------------
__global__ void count_den_kernel(const int* __restrict__ pv, const int* __restrict__ pe,
                                 const float* __restrict__ wv2e, const float* __restrict__ we2v) {
    int i = blockIdx.x * blockDim.x + threadIdx.x;
    if (i >= NNZp) return;
    int v = pv[i], e = pe[i];
    atomicAdd(&g_cnt_e[e], 1);
    atomicAdd(&g_den_e[e], wv2e[i]);
    atomicAdd(&g_cnt_v[v], 1);
    atomicAdd(&g_den_v[v], we2v[i]);
}

__global__ void invden_kernel() {
    int i = blockIdx.x * blockDim.x + threadIdx.x;
    if (i < NE) g_invdene[i] = 1.f / fmaxf(g_den_e[i], 1e-12f);
    if (i < NV) g_invdenv[i] = 1.f / fmaxf(g_den_v[i], 1e-12f);
}

// ---------------- scan (1024 elems per block) ----------------
__global__ void scan_chunk_kernel(const int* __restrict__ in, int* __restrict__ incl,
                                  int* __restrict__ bsums, int n) {
    __shared__ int sh[256];
    int t = threadIdx.x;
    int base = blockIdx.x * 1024 + t * 4;
    int a0 = (base + 0 < n) ? in[base + 0] : 0;
    int a1 = (base + 1 < n) ? in[base + 1] : 0;
    int a2 = (base + 2 < n) ? in[base + 2] : 0;
    int a3 = (base + 3 < n) ? in[base + 3] : 0;
    int s1 = a0 + a1, s2 = s1 + a2, s3 = s2 + a3;
    sh[t] = s3;
    __syncthreads();
#pragma unroll
    for (int o = 1; o < 256; o <<= 1) {
        int v = (t >= o) ? sh[t - o] : 0;
        __syncthreads();
        sh[t] += v;
        __syncthreads();
    }
    int excl = sh[t] - s3;
    if (base + 0 < n) incl[base + 0] = excl + a0;
    if (base + 1 < n) incl[base + 1] = excl + s1;
    if (base + 2 < n) incl[base + 2] = excl + s2;
    if (base + 3 < n) incl[base + 3] = excl + s3;
    if (t == 255) bsums[blockIdx.x] = sh[255];
}

__global__ void scan_bsums_kernel(int* __restrict__ bsums, int nb) {
    __shared__ int sh[256];
    int t = threadIdx.x;
    int v = (t < nb) ? bsums[t] : 0;
    sh[t] = v;
    __syncthreads();
#pragma unroll
    for (int o = 1; o < 256; o <<= 1) {
        int u = (t >= o) ? sh[t - o] : 0;
        __syncthreads();
        sh[t] += u;
        __syncthreads();
    }
    if (t < nb) bsums[t] = sh[t] - v;   // exclusive
}

__global__ void finalize_off_kernel(const int* __restrict__ incl, const int* __restrict__ bexcl,
                                    int* __restrict__ off, int* __restrict__ cur, int n) {
    int i = blockIdx.x * blockDim.x + threadIdx.x;
    if (i >= n) return;
    int val = incl[i] + bexcl[i >> 10];
    off[i + 1] = val;
    cur[i + 1] = val;
    if (i == 0) { off[0] = 0; cur[0] = 0; }
}

// ---------------- fill CSR-style permuted arrays ----------------
__global__ void fill_kernel(const int* __restrict__ pv, const int* __restrict__ pe,
                            const float* __restrict__ wv2e, const float* __restrict__ we2v) {
    int i = blockIdx.x * blockDim.x + threadIdx.x;
    if (i >= NNZp) return;
    int v = pv[i], e = pe[i];
    int pe_pos = atomicAdd(&g_cur_e[e], 1);
    g_esrc[pe_pos] = v;
    g_ew[pe_pos]   = wv2e[i];
    int pv_pos = atomicAdd(&g_cur_v[v], 1);
    g_vsrc[pv_pos] = e;
    g_vw[pv_pos]   = we2v[i];
}

// ---------------- W prep: transpose + bf16 hi/lo split ----------------
__global__ void wprep_kernel(const float* __restrict__ Wm) {
    int i = blockIdx.x * blockDim.x + threadIdx.x;  // over DD*FIN
    if (i >= DD * FIN) return;
    int n = i / FIN, k = i % FIN;
    float w = Wm[(size_t)k * DD + n];
    __nv_bfloat16 hi = __float2bfloat16_rn(w);
    __nv_bfloat16 lo = __float2bfloat16_rn(w - __bfloat162float(hi));
    g_Wth[i] = hi;
    g_Wtl[i] = lo;
}

// ---------------- bf16-split tensor-core GEMM:  x0 = feats @ W + b ----------------
// BM=128, BN=128(=DD), BK=32, 256 threads = 8 warps (4 m x 2 n), warp tile 32x64.
// C = Ah*Bh + Ah*Bl + Al*Bh  (fp32 accumulate; lo*lo dropped, err ~1e-5)
#define SK 40   // padded smem stride in halves (conflict-free)
__global__ void __launch_bounds__(256) gemm_bf16_kernel(const float* __restrict__ A,
                                                        const float* __restrict__ bias,
                                                        float* __restrict__ C) {
    __shared__ __nv_bfloat16 Ah[128][SK], Al[128][SK];
    __shared__ __nv_bfloat16 Bh[128][SK], Bl[128][SK];

    const int tid  = threadIdx.x;
    const int lane = tid & 31;
    const int wid  = tid >> 5;
    const int warp_m = wid & 3;        // 0..3 -> 32-row slabs
    const int warp_n = wid >> 2;       // 0..1 -> 64-col slabs
    const int brow = blockIdx.x * 128;

    float acc[2][8][4];
#pragma unroll
    for (int mt = 0; mt < 2; mt++)
#pragma unroll
        for (int nt = 0; nt < 8; nt++)
#pragma unroll
            for (int q = 0; q < 4; q++) acc[mt][nt][q] = 0.f;

    for (int k0 = 0; k0 < FIN; k0 += 32) {
        // --- A tile: 128 rows x 32 floats -> split hi/lo bf16 ---
#pragma unroll
        for (int ii = 0; ii < 4; ii++) {
            int id  = tid + ii * 256;       // 0..1023
            int row = id >> 3;
            int c   = (id & 7) * 4;
            int gr  = brow + row;
            float4 v = make_float4(0.f, 0.f, 0.f, 0.f);
            if (gr < NV) v = *(const float4*)(A + (size_t)gr * FIN + k0 + c);
            __nv_bfloat16 hx = __float2bfloat16_rn(v.x);
            __nv_bfloat16 hy = __float2bfloat16_rn(v.y);
            __nv_bfloat16 hz = __float2bfloat16_rn(v.z);
            __nv_bfloat16 hw = __float2bfloat16_rn(v.w);
            __nv_bfloat16 lx = __float2bfloat16_rn(v.x - __bfloat162float(hx));
            __nv_bfloat16 ly = __float2bfloat16_rn(v.y - __bfloat162float(hy));
            __nv_bfloat16 lz = __float2bfloat16_rn(v.z - __bfloat162float(hz));
            __nv_bfloat16 lw = __float2bfloat16_rn(v.w - __bfloat162float(hw));
            *(__nv_bfloat162*)&Ah[row][c]     = __halves2bfloat162(hx, hy);
            *(__nv_bfloat162*)&Ah[row][c + 2] = __halves2bfloat162(hz, hw);
            *(__nv_bfloat162*)&Al[row][c]     = __halves2bfloat162(lx, ly);
            *(__nv_bfloat162*)&Al[row][c + 2] = __halves2bfloat162(lz, lw);
        }
        // --- B tile: Wt[n][k0..k0+31] bf16, coalesced copy ---
#pragma unroll
        for (int ii = 0; ii < 2; ii++) {
            int id  = tid + ii * 256;       // 0..511
            int n   = id >> 2;
            int seg = (id & 3) * 8;         // halves
            *(uint4*)&Bh[n][seg] = *(const uint4*)&g_Wth[(size_t)n * FIN + k0 + seg];
            *(uint4*)&Bl[n][seg] = *(const uint4*)&g_Wtl[(size_t)n * FIN + k0 + seg];
        }
        __syncthreads();

#pragma unroll
        for (int kk = 0; kk < 32; kk += 16) {
            const int c0 = kk + (lane & 3) * 2;
            const int ra = warp_m * 32 + (lane >> 2);
            // A fragments (hi & lo)
            unsigned int ah[2][4], al[2][4];
#pragma unroll
            for (int mt = 0; mt < 2; mt++) {
                int r = ra + mt * 16;
                ah[mt][0] = *(const unsigned int*)&Ah[r][c0];
                ah[mt][1] = *(const unsigned int*)&Ah[r + 8][c0];
                ah[mt][2] = *(const unsigned int*)&Ah[r][c0 + 8];
                ah[mt][3] = *(const unsigned int*)&Ah[r + 8][c0 + 8];
                al[mt][0] = *(const unsigned int*)&Al[r][c0];
                al[mt][1] = *(const unsigned int*)&Al[r + 8][c0];
                al[mt][2] = *(const unsigned int*)&Al[r][c0 + 8];
                al[mt][3] = *(const unsigned int*)&Al[r + 8][c0 + 8];
            }
#pragma unroll
            for (int nt = 0; nt < 8; nt++) {
                int n = warp_n * 64 + nt * 8 + (lane >> 2);
                unsigned int bh0 = *(const unsigned int*)&Bh[n][c0];
                unsigned int bh1 = *(const unsigned int*)&Bh[n][c0 + 8];
                unsigned int bl0 = *(const unsigned int*)&Bl[n][c0];
                unsigned int bl1 = *(const unsigned int*)&Bl[n][c0 + 8];
#pragma unroll
                for (int mt = 0; mt < 2; mt++) {
                    float* d = acc[mt][nt];
                    asm volatile("mma.sync.aligned.m16n8k16.row.col.f32.bf16.bf16.f32 "
                        "{%0,%1,%2,%3}, {%4,%5,%6,%7}, {%8,%9}, {%0,%1,%2,%3};"
                        : "+f"(d[0]), "+f"(d[1]), "+f"(d[2]), "+f"(d[3])
                        : "r"(ah[mt][0]), "r"(ah[mt][1]), "r"(ah[mt][2]), "r"(ah[mt][3]),
                          "r"(bh0), "r"(bh1));
                    asm volatile("mma.sync.aligned.m16n8k16.row.col.f32.bf16.bf16.f32 "
                        "{%0,%1,%2,%3}, {%4,%5,%6,%7}, {%8,%9}, {%0,%1,%2,%3};"
                        : "+f"(d[0]), "+f"(d[1]), "+f"(d[2]), "+f"(d[3])
                        : "r"(ah[mt][0]), "r"(ah[mt][1]), "r"(ah[mt][2]), "r"(ah[mt][3]),
                          "r"(bl0), "r"(bl1));
                    asm volatile("mma.sync.aligned.m16n8k16.row.col.f32.bf16.bf16.f32 "
                        "{%0,%1,%2,%3}, {%4,%5,%6,%7}, {%8,%9}, {%0,%1,%2,%3};"
                        : "+f"(d[0]), "+f"(d[1]), "+f"(d[2]), "+f"(d[3])
                        : "r"(al[mt][0]), "r"(al[mt][1]), "r"(al[mt][2]), "r"(al[mt][3]),
                          "r"(bh0), "r"(bh1));
                }
            }
        }
        __syncthreads();
    }

    // ---- epilogue: acc + bias -> C ----
    const int rbase = brow + warp_m * 32 + (lane >> 2);
    const int cbase = warp_n * 64 + (lane & 3) * 2;
#pragma unroll
    for (int nt = 0; nt < 8; nt++) {
        int col = cbase + nt * 8;
        float b0 = __ldg(bias + col);
        float b1 = __ldg(bias + col + 1);
#pragma unroll
        for (int mt = 0; mt < 2; mt++) {
            int r0 = rbase + mt * 16;
            if (r0 < NV) {
                float2 o = make_float2(acc[mt][nt][0] + b0, acc[mt][nt][1] + b1);
                *(float2*)(C + (size_t)r0 * DD + col) = o;
            }
            int r1 = r0 + 8;
            if (r1 < NV) {
                float2 o = make_float2(acc[mt][nt][2] + b0, acc[mt][nt][3] + b1);
                *(float2*)(C + (size_t)r1 * DD + col) = o;
            }
        }
    }
}

// ---------------- gather-based weighted-mean aggregation ----------------
__global__ void __launch_bounds__(256) agg_kernel(const float4* __restrict__ src,
                                                  float4* __restrict__ dst,
                                                  const int* __restrict__ off,
                                                  const int* __restrict__ sidx,
                                                  const float* __restrict__ wt,
                                                  const float* __restrict__ invden,
                                                  int ndst) {
    int t = blockIdx.x * blockDim.x + threadIdx.x;
    int r = t >> 5;
    int lane = t & 31;
    if (r >= ndst) return;
    int j0 = __ldg(off + r);
    int j1 = __ldg(off + r + 1);
    float4 acc = make_float4(0.f, 0.f, 0.f, 0.f);
    int j = j0;
    for (; j + 2 <= j1; j += 2) {
        int   s0 = __ldg(sidx + j),   s1 = __ldg(sidx + j + 1);
        float w0 = __ldg(wt + j),     w1 = __ldg(wt + j + 1);
        float4 v0 = __ldg(src + (size_t)s0 * 32 + lane);
        float4 v1 = __ldg(src + (size_t)s1 * 32 + lane);
        acc.x = fmaf(w0, v0.x, acc.x); acc.y = fmaf(w0, v0.y, acc.y);
        acc.z = fmaf(w0, v0.z, acc.z); acc.w = fmaf(w0, v0.w, acc.w);
        acc.x = fmaf(w1, v1.x, acc.x); acc.y = fmaf(w1, v1.y, acc.y);
        acc.z = fmaf(w1, v1.z, acc.z); acc.w = fmaf(w1, v1.w, acc.w);
    }
    if (j < j1) {
        int   s0 = __ldg(sidx + j);
        float w0 = __ldg(wt + j);
        float4 v0 = __ldg(src + (size_t)s0 * 32 + lane);
        acc.x = fmaf(w0, v0.x, acc.x); acc.y = fmaf(w0, v0.y, acc.y);
        acc.z = fmaf(w0, v0.z, acc.z); acc.w = fmaf(w0, v0.w, acc.w);
    }
    float sc = __ldg(invden + r);
    acc.x *= sc; acc.y *= sc; acc.z *= sc; acc.w *= sc;
    dst[(size_t)r * 32 + lane] = acc;
}

// ---------------- fused softmax ----------------
__global__ void __launch_bounds__(256) softmax_kernel(const float4* __restrict__ x,
                                                      float4* __restrict__ out) {
    int t = blockIdx.x * blockDim.x + threadIdx.x;
    int r = t >> 5;
    int lane = t & 31;
    if (r >= NV) return;
    float4 v = __ldg(x + (size_t)r * 32 + lane);
    float m = fmaxf(fmaxf(v.x, v.y), fmaxf(v.z, v.w));
#pragma unroll
    for (int o = 16; o; o >>= 1) m = fmaxf(m, __shfl_xor_sync(0xffffffffu, m, o));
    float4 e;
    e.x = __expf(v.x - m); e.y = __expf(v.y - m);
    e.z = __expf(v.z - m); e.w = __expf(v.w - m);
    float s = e.x + e.y + e.z + e.w;
#pragma unroll
    for (int o = 16; o; o >>= 1) s += __shfl_xor_sync(0xffffffffu, s, o);
    float inv = 1.f / s;
    out[(size_t)r * 32 + lane] = make_float4(e.x * inv, e.y * inv, e.z * inv, e.w * inv);
}

// ---------------- launch ----------------
extern "C" void kernel_launch(void* const* d_in, const int* in_sizes, int n_in,
                              void* d_out, int out_size) {
    const float* feats = (const float*)d_in[0];
    const float* Wm    = (const float*)d_in[1];
    const float* bias  = (const float*)d_in[2];
    const float* v2e_w = (const float*)d_in[3];
    const float* e2v_w = (const float*)d_in[4];
    const int*   pv    = (const int*)d_in[5];
    const int*   pe    = (const int*)d_in[6];
    float* out = (float*)d_out;

    float *x0, *x1, *y, *invdene, *invdenv, *ew, *vw;
    int *cnt_e, *cnt_v, *off_e, *off_v, *cur_e, *cur_v, *esrc, *vsrc, *scan_tmp, *bsums;
    cudaGetSymbolAddress((void**)&x0, g_x0);
    cudaGetSymbolAddress((void**)&x1, g_x1);
    cudaGetSymbolAddress((void**)&y,  g_y);
    cudaGetSymbolAddress((void**)&invdene, g_invdene);
    cudaGetSymbolAddress((void**)&invdenv, g_invdenv);
    cudaGetSymbolAddress((void**)&ew, g_ew);
    cudaGetSymbolAddress((void**)&vw, g_vw);
    cudaGetSymbolAddress((void**)&cnt_e, g_cnt_e);
    cudaGetSymbolAddress((void**)&cnt_v, g_cnt_v);
    cudaGetSymbolAddress((void**)&off_e, g_off_e);
    cudaGetSymbolAddress((void**)&off_v, g_off_v);
    cudaGetSymbolAddress((void**)&cur_e, g_cur_e);
    cudaGetSymbolAddress((void**)&cur_v, g_cur_v);
    cudaGetSymbolAddress((void**)&esrc, g_esrc);
    cudaGetSymbolAddress((void**)&vsrc, g_vsrc);
    cudaGetSymbolAddress((void**)&scan_tmp, g_scan_tmp);
    cudaGetSymbolAddress((void**)&bsums, g_bsums);

    const int TB = 256;
    const int nnzBlocks = (NNZp + TB - 1) / TB;

    // 1) counts + denominators (+ W prep)
    zero_small_kernel<<<(NV + TB - 1) / TB, TB>>>();
    wprep_kernel<<<(DD * FIN + TB - 1) / TB, TB>>>(Wm);
    count_den_kernel<<<nnzBlocks, TB>>>(pv, pe, v2e_w, e2v_w);
    invden_kernel<<<(NV + TB - 1) / TB, TB>>>();

    // 2) offsets via scan
    {
        int nb = (NE + 1023) / 1024;
        scan_chunk_kernel<<<nb, 256>>>(cnt_e, scan_tmp, bsums, NE);
        scan_bsums_kernel<<<1, 256>>>(bsums, nb);
        finalize_off_kernel<<<(NE + TB - 1) / TB, TB>>>(scan_tmp, bsums, off_e, cur_e, NE);
    }
    {
        int nb = (NV + 1023) / 1024;
        scan_chunk_kernel<<<nb, 256>>>(cnt_v, scan_tmp, bsums, NV);
        scan_bsums_kernel<<<1, 256>>>(bsums, nb);
        finalize_off_kernel<<<(NV + TB - 1) / TB, TB>>>(scan_tmp, bsums, off_v, cur_v, NV);
    }

    // 3) fill grouped arrays
    fill_kernel<<<nnzBlocks, TB>>>(pv, pe, v2e_w, e2v_w);

    // 4) x0 = feats @ W + b  (bf16-split tensor cores)
    gemm_bf16_kernel<<<(NV + 127) / 128, TB>>>(feats, bias, x0);

    // 5) two hops of weighted-mean aggregation
    const int eBlocks = (NE * 32) / TB;
    const int vBlocks = (NV * 32) / TB;
    agg_kernel<<<eBlocks, TB>>>((const float4*)x0, (float4*)y,  off_e, esrc, ew, invdene, NE);
    agg_kernel<<<vBlocks, TB>>>((const float4*)y,  (float4*)x1, off_v, vsrc, vw, invdenv, NV);
    agg_kernel<<<eBlocks, TB>>>((const float4*)x1, (float4*)y,  off_e, esrc, ew, invdene, NE);
    agg_kernel<<<vBlocks, TB>>>((const float4*)y,  (float4*)x0, off_v, vsrc, vw, invdenv, NV);

    // 6) softmax
    softmax_kernel<<<vBlocks, TB>>>((const float4*)x0, (float4*)out);
}